// round 13
// baseline (speedup 1.0000x reference)
#include <cuda_runtime.h>
#include <cstdint>

// Custom_Decoder fused GEMM + overlap_add.
// Warp-private cp.async ring (NO block barriers in main loop), P=2 pairs x
// R=8 row-pairs per thread (32 packed accumulators).
//
// out[bc,16p+r]   = x[2p].wt[r]   + x[2p-1].wt[8+r]     (r=0..7)
// out[bc,16p+8+r] = x[2p+1].wt[r] + x[2p]  .wt[8+r]
//
// Warp tile = 8 pairs (frames 16tl-1 .. 16tl+15, 17 rows, OOB zero-filled).
// Stage = K-sixteenth (32 floats): slot = 17 rows x 128 B = 2176 B.
// 2000 warps (250 CTAs x 8) x 2 tiles = 4000 tiles = 32000 pairs exactly.

#define E_DIM 512
#define FRAMES 3999
#define OUT_T 32000
#define NTH 256
#define GRID 250
#define TPB 250                    // tiles per bc (8 pairs each)
#define SLOT 2176                  // 17 * 128
#define W_BYTES (16*E_DIM*4)       // 32768
#define RING_PW (3*SLOT)           // 6528 per warp
#define SMEM_TOTAL (W_BYTES + 8*RING_PW)   // 84992 -> 2 CTAs/SM

typedef unsigned long long ull;

__device__ __forceinline__ void ffma2(ull &d, ull a, ull b) {
    asm("fma.rn.f32x2 %0, %1, %2, %0;" : "+l"(d) : "l"(a), "l"(b));
}
__device__ __forceinline__ float flo(ull v){ return __uint_as_float((unsigned)(v & 0xffffffffu)); }
__device__ __forceinline__ float fhi(ull v){ return __uint_as_float((unsigned)(v >> 32)); }

__device__ __forceinline__ void cp16(uint32_t sa, const void* g) {
    asm volatile("cp.async.cg.shared.global [%0], [%1], 16;" :: "r"(sa), "l"(g));
}

// fill stage s (tile = wg*2 + s/16, k-granule g = s%16) into warp slot s%3.
// Warp-collective, warp-private. Always commits.
__device__ __forceinline__ void fill(uint32_t ringw, const float* __restrict__ x,
                                     int s, int wg, int lane)
{
    if (s < 32) {
        const int t  = wg * 2 + (s >> 4);
        const int g  = s & 15;
        const int bc = t / TPB;
        const int tl = t - bc * TPB;
        const int f0 = 16 * tl - 1;
        const float* xb = x + (size_t)bc * FRAMES * E_DIM + g * 32;
        uint32_t slot = ringw + (uint32_t)(s % 3) * SLOT;
#pragma unroll
        for (int i = 0; i < 5; i++) {
            int c = lane + i * 32;               // 136 chunks of 16B
            if (i < 4 || lane < 8) {
                int f = f0 + (c >> 3);           // 8 chunks per 128B row
                uint32_t sa = slot + c * 16;
                if ((unsigned)f < FRAMES) cp16(sa, xb + (size_t)f * E_DIM + (c & 7) * 4);
                else asm volatile("st.shared.v4.b32 [%0], {%1,%1,%1,%1};" :: "r"(sa), "r"(0));
            }
        }
    }
    asm volatile("cp.async.commit_group;");
}

__global__ __launch_bounds__(NTH, 2)
void decoder_wp(const float* __restrict__ x,
                const float* __restrict__ wt,
                float* __restrict__ out)
{
    extern __shared__ __align__(16) char smem[];
    float* wsm = (float*)smem;

    const int tid  = threadIdx.x;
    const int w    = tid >> 5;
    const int lane = tid & 31;
    const int ks   = lane & 7;                  // k slice (floats 32g + 4ks + 0..3)
    const int gl   = lane >> 3;                 // 0..3: which 2-pair group
    const int wg   = blockIdx.x * 8 + w;        // 0..1999

    uint32_t ringw = (uint32_t)__cvta_generic_to_shared(smem + W_BYTES) + w * RING_PW;
    const char* ringp = smem + W_BYTES + w * RING_PW;

    // stage weights once (coalesced float4), then the only block barrier
#pragma unroll
    for (int i = 0; i < (16 * E_DIM) / (4 * NTH); i++) {
        int idx = (i * NTH + tid) * 4;
        *(float4*)(wsm + idx) = *(const float4*)(wt + idx);
    }
    __syncthreads();

    fill(ringw, x, 0, wg, lane);
    fill(ringw, x, 1, wg, lane);
    fill(ringw, x, 2, wg, lane);

#pragma unroll 1
    for (int t2 = 0; t2 < 2; t2++) {
        const int t  = wg * 2 + t2;
        const int bc = t / TPB;
        const int tl = t - bc * TPB;
        const int p0 = t * 8 - bc * OUT_T / 16 + 2 * gl;   // local pair = 8*tl + 2*gl
        // (8*tl + 2*gl; written this way to keep ints small)

        ull a0[8], a1[8], b0[8], b1[8];
#pragma unroll
        for (int j = 0; j < 8; j++) { a0[j]=0; a1[j]=0; b0[j]=0; b1[j]=0; }

#pragma unroll 1
        for (int g = 0; g < 16; g++) {
            const int s = t2 * 16 + g;
            asm volatile("cp.async.wait_group 2;" ::: "memory");   // fill(s) done

            // rows 4gl..4gl+4 hold frames 2p-1..2p+3 for p = 8tl+2gl
            const char* xg = ringp + (s % 3) * SLOT + gl * 512 + ks * 16;
            ulonglong2 xm1 = *(const ulonglong2*)(xg);
            ulonglong2 x0  = *(const ulonglong2*)(xg + 128);
            ulonglong2 x1  = *(const ulonglong2*)(xg + 256);
            ulonglong2 x2  = *(const ulonglong2*)(xg + 384);
            ulonglong2 x3  = *(const ulonglong2*)(xg + 512);

            const float* wb = wsm + g * 32 + ks * 4;
#pragma unroll
            for (int j = 0; j < 8; j++) {
                ulonglong2 wl = *(const ulonglong2*)(wb + j * E_DIM);
                ulonglong2 wh = *(const ulonglong2*)(wb + (j + 8) * E_DIM);
                ffma2(a0[j], x0.x,  wl.x);  ffma2(a0[j], x0.y,  wl.y);
                ffma2(a0[j], xm1.x, wh.x);  ffma2(a0[j], xm1.y, wh.y);
                ffma2(a1[j], x1.x,  wl.x);  ffma2(a1[j], x1.y,  wl.y);
                ffma2(a1[j], x0.x,  wh.x);  ffma2(a1[j], x0.y,  wh.y);
                ffma2(b0[j], x2.x,  wl.x);  ffma2(b0[j], x2.y,  wl.y);
                ffma2(b0[j], x1.x,  wh.x);  ffma2(b0[j], x1.y,  wh.y);
                ffma2(b1[j], x3.x,  wl.x);  ffma2(b1[j], x3.y,  wl.y);
                ffma2(b1[j], x2.x,  wh.x);  ffma2(b1[j], x2.y,  wh.y);
            }
            fill(ringw, x, s + 3, wg, lane);     // refill slot consumed this stage
        }

        // epilogue: packed horizontal add + reduce over 8 ks lanes
        float sv[32];
#pragma unroll
        for (int j = 0; j < 8; j++) {
            sv[j]      = flo(a0[j]) + fhi(a0[j]);
            sv[8 + j]  = flo(a1[j]) + fhi(a1[j]);
            sv[16 + j] = flo(b0[j]) + fhi(b0[j]);
            sv[24 + j] = flo(b1[j]) + fhi(b1[j]);
        }
#pragma unroll
        for (int m = 1; m <= 4; m <<= 1)
#pragma unroll
            for (int j = 0; j < 32; j++)
                sv[j] += __shfl_xor_sync(0xffffffffu, sv[j], m);

        if (ks == 0) {
            // pairs p = 8tl+2gl, 8tl+2gl+1 -> 32 contiguous floats
            float* o = out + (size_t)bc * OUT_T + (size_t)(8 * tl + 2 * gl) * 16;
#pragma unroll
            for (int q = 0; q < 8; q++)
                *(float4*)(o + 4 * q) =
                    make_float4(sv[4*q], sv[4*q+1], sv[4*q+2], sv[4*q+3]);
        }
        (void)p0;
    }
}

extern "C" void kernel_launch(void* const* d_in, const int* in_sizes, int n_in,
                              void* d_out, int out_size)
{
    const float *x, *wt;
    if (in_sizes[0] > in_sizes[1]) { x = (const float*)d_in[0]; wt = (const float*)d_in[1]; }
    else                           { x = (const float*)d_in[1]; wt = (const float*)d_in[0]; }

    cudaFuncSetAttribute(decoder_wp,
                         cudaFuncAttributeMaxDynamicSharedMemorySize, SMEM_TOTAL);

    decoder_wp<<<GRID, NTH, SMEM_TOTAL>>>(x, wt, (float*)d_out);
}

// round 16
// speedup vs baseline: 1.5386x; 1.5386x over previous
#include <cuda_runtime.h>
#include <cstdint>

// Custom_Decoder fused GEMM + overlap_add; R7 schedule (quarter-K stages,
// 3-slot cp.async ring, amortized fills) + fat thread tile: 2 pairs x 16 rows
// (32 packed accumulators) -> 21 LDS.128 per 128 FFMA2.
//
// out[bc,16p+r]   = x[2p].wt[r]   + x[2p-1].wt[8+r]     (r=0..7)
// out[bc,16p+8+r] = x[2p+1].wt[r] + x[2p]  .wt[8+r]
//
// 128 blocks x 4 units; unit = 64 pairs (128 frames) of one bc (32 units/bc,
// OOB frames zero-filled, stores predicated).
// Stage = (unit, k-quarter): slot = 129 rows x 512 B.

#define E_DIM 512
#define QUART 128
#define FRAMES 3999
#define PAIRS 2000
#define OUT_T 32000
#define GRID 128
#define UNITS_PER_BLOCK 4
#define NSTAGES (4*UNITS_PER_BLOCK)    // 16
#define NTH 256
#define SLOT_BYTES (129*512)           // 66048
#define W_BYTES (16*E_DIM*4)           // 32768
#define SMEM_TOTAL (W_BYTES + 3*SLOT_BYTES)   // 230912 <= 232448 optin
#define CHUNKS (SLOT_BYTES/16)         // 4128

typedef unsigned long long ull;

__device__ __forceinline__ void ffma2(ull &d, ull a, ull b) {
    asm("fma.rn.f32x2 %0, %1, %2, %0;" : "+l"(d) : "l"(a), "l"(b));
}
__device__ __forceinline__ float flo(ull v){ return __uint_as_float((unsigned)(v & 0xffffffffu)); }
__device__ __forceinline__ float fhi(ull v){ return __uint_as_float((unsigned)(v >> 32)); }

__device__ __forceinline__ void cp16(uint32_t sa, const void* g) {
    asm volatile("cp.async.cg.shared.global [%0], [%1], 16;" :: "r"(sa), "l"(g));
}
__device__ __forceinline__ void cp_commit() { asm volatile("cp.async.commit_group;"); }
__device__ __forceinline__ void cp_wait2()  { asm volatile("cp.async.wait_group 2;"); }

// stage s: unit iu = s/4, quarter q = s&3. Always commits (empty groups past
// the end keep wait_group(2) bookkeeping uniform). Address math amortized
// over 4128 cp.async chunks.
__device__ __forceinline__ void issue_stage(char* ring, const float* __restrict__ x,
                                            int s, int tid, int bx)
{
    if (s < NSTAGES) {
        const int u  = bx * UNITS_PER_BLOCK + (s >> 2);   // < 512
        const int q  = s & 3;
        const int bc = u >> 5;               // 32 units per bc
        const int U  = u & 31;
        const int f0 = 128 * U - 1;          // first staged frame (may be OOB)
        const float* xb = x + (size_t)bc * FRAMES * E_DIM + q * QUART;
        char* slot = ring + (s % 3) * SLOT_BYTES;
        uint32_t sbase = (uint32_t)__cvta_generic_to_shared(slot);
#pragma unroll
        for (int i = 0; i < 17; i++) {
            int c = tid + i * NTH;
            if (i < 16 || c < CHUNKS) {
                int f = f0 + (c >> 5);       // 32 chunks of 16B per 512B row
                uint32_t sa = sbase + c * 16;
                if ((unsigned)f < FRAMES) {
                    cp16(sa, xb + (size_t)f * E_DIM + (c & 31) * 4);
                } else {
                    asm volatile("st.shared.v4.b32 [%0], {%1,%1,%1,%1};" :: "r"(sa), "r"(0));
                }
            }
        }
    }
    cp_commit();
}

__global__ __launch_bounds__(NTH)
void decoder_fat(const float* __restrict__ x,
                 const float* __restrict__ wt,
                 float* __restrict__ out)
{
    extern __shared__ __align__(16) char smem[];
    float* wsm = (float*)smem;
    char*  ring = smem + W_BYTES;

    const int tid = threadIdx.x;
    const int bx  = blockIdx.x;

    // stage weights (8 float4 per thread)
#pragma unroll
    for (int i = 0; i < (16 * E_DIM) / (4 * NTH); i++) {
        int idx = (i * NTH + tid) * 4;
        *(float4*)(wsm + idx) = *(const float4*)(wt + idx);
    }

    // prologue: prefetch stages 0,1,2
    issue_stage(ring, x, 0, tid, bx);
    issue_stage(ring, x, 1, tid, bx);
    issue_stage(ring, x, 2, tid, bx);

    const int lane = tid & 31;
    const int ks   = lane & 7;          // lane bits 0-2: k slice
    const int gl   = lane >> 3;         // lane bits 3-4: 2-pair group in warp
    const int gloc = (tid >> 5) * 4 + gl;    // group 0..31 within unit
    // thread tile: pairs 2*gloc, 2*gloc+1 ; ALL 16 weight rows

#pragma unroll 1
    for (int iu = 0; iu < UNITS_PER_BLOCK; iu++) {
        const int u  = bx * UNITS_PER_BLOCK + iu;
        const int bc = u >> 5;
        const int U  = u & 31;
        const int p0 = 64 * U + 2 * gloc;        // thread's first pair

        ull a0[8], a1[8], b0[8], b1[8];
#pragma unroll
        for (int j = 0; j < 8; j++) { a0[j]=0; a1[j]=0; b0[j]=0; b1[j]=0; }

#pragma unroll 1
        for (int q = 0; q < 4; q++) {
            const int s = 4 * iu + q;
            cp_wait2();
            __syncthreads();                     // stage s resident for all

            // rows 4*gloc..4*gloc+4 hold frames 2p0-1..2p0+3 (zeros OOB)
            const char* xg = ring + (s % 3) * SLOT_BYTES + (4 * gloc) * 512 + ks * 16;
            const float* wq = wsm + q * QUART + ks * 4;

#pragma unroll
            for (int i = 0; i < 4; i++) {
                const int xo = i * 128;          // 32 floats per granule
                ulonglong2 xm1 = *(const ulonglong2*)(xg +           xo);
                ulonglong2 x0  = *(const ulonglong2*)(xg + 1 * 512 + xo);
                ulonglong2 x1  = *(const ulonglong2*)(xg + 2 * 512 + xo);
                ulonglong2 x2  = *(const ulonglong2*)(xg + 3 * 512 + xo);
                ulonglong2 x3  = *(const ulonglong2*)(xg + 4 * 512 + xo);
#pragma unroll
                for (int j = 0; j < 8; j++) {
                    ulonglong2 wl = *(const ulonglong2*)(wq + j * E_DIM + i * 32);
                    ulonglong2 wh = *(const ulonglong2*)(wq + (j + 8) * E_DIM + i * 32);
                    ffma2(a0[j], x0.x,  wl.x);  ffma2(a0[j], x0.y,  wl.y);
                    ffma2(a0[j], xm1.x, wh.x);  ffma2(a0[j], xm1.y, wh.y);
                    ffma2(a1[j], x1.x,  wl.x);  ffma2(a1[j], x1.y,  wl.y);
                    ffma2(a1[j], x0.x,  wh.x);  ffma2(a1[j], x0.y,  wh.y);
                    ffma2(b0[j], x2.x,  wl.x);  ffma2(b0[j], x2.y,  wl.y);
                    ffma2(b0[j], x1.x,  wh.x);  ffma2(b0[j], x1.y,  wh.y);
                    ffma2(b1[j], x3.x,  wl.x);  ffma2(b1[j], x3.y,  wl.y);
                    ffma2(b1[j], x2.x,  wh.x);  ffma2(b1[j], x2.y,  wh.y);
                }
            }
            __syncthreads();                     // slot fully consumed
            issue_stage(ring, x, s + 3, tid, bx);   // refill (or empty commit)
        }

        // epilogue: packed horizontal add, reduce over the 8 ks lanes
        // (shfl_xor 1,2,4 stays within the ks octet; gl bits untouched)
        float sv[32];
#pragma unroll
        for (int j = 0; j < 8; j++) {
            sv[j]      = flo(a0[j]) + fhi(a0[j]);
            sv[8 + j]  = flo(a1[j]) + fhi(a1[j]);
            sv[16 + j] = flo(b0[j]) + fhi(b0[j]);
            sv[24 + j] = flo(b1[j]) + fhi(b1[j]);
        }
#pragma unroll
        for (int m = 1; m <= 4; m <<= 1)
#pragma unroll
            for (int j = 0; j < 32; j++)
                sv[j] += __shfl_xor_sync(0xffffffffu, sv[j], m);

        if (ks == 0 && p0 < PAIRS) {
            float* o = out + (size_t)bc * OUT_T + (size_t)p0 * 16;  // 32 floats
#pragma unroll
            for (int qq = 0; qq < 8; qq++)
                *(float4*)(o + 4 * qq) =
                    make_float4(sv[4*qq], sv[4*qq+1], sv[4*qq+2], sv[4*qq+3]);
        }
    }
}

extern "C" void kernel_launch(void* const* d_in, const int* in_sizes, int n_in,
                              void* d_out, int out_size)
{
    const float *x, *wt;
    if (in_sizes[0] > in_sizes[1]) { x = (const float*)d_in[0]; wt = (const float*)d_in[1]; }
    else                           { x = (const float*)d_in[1]; wt = (const float*)d_in[0]; }

    cudaFuncSetAttribute(decoder_fat,
                         cudaFuncAttributeMaxDynamicSharedMemorySize, SMEM_TOTAL);

    decoder_fat<<<GRID, NTH, SMEM_TOTAL>>>(x, wt, (float*)d_out);
}

// round 17
// speedup vs baseline: 1.5877x; 1.0319x over previous
#include <cuda_runtime.h>
#include <cstdint>

// Custom_Decoder fused GEMM + overlap_add.
// Fat thread tile (2 pairs x 16 rows, 32 packed accumulators) + 2-slot
// K-eighth cp.async ring -> smem 98816 B -> 2 CTAs/SM (16 warps/SM).
//
// out[bc,16p+r]   = x[2p].wt[r]   + x[2p-1].wt[8+r]     (r=0..7)
// out[bc,16p+8+r] = x[2p+1].wt[r] + x[2p]  .wt[8+r]
//
// 256 blocks x 2 units; unit = 64 pairs (128 frames) of one bc (32 units/bc,
// OOB frames zero-filled, stores predicated).
// Stage = (unit, k-eighth): slot = 129 rows x 256 B.

#define E_DIM 512
#define FRAMES 3999
#define PAIRS 2000
#define OUT_T 32000
#define GRID 256
#define UNITS_PER_BLOCK 2
#define NSTAGES (8*UNITS_PER_BLOCK)    // 16
#define NTH 256
#define SLOT_BYTES (129*256)           // 33024
#define W_BYTES (16*E_DIM*4)           // 32768
#define SMEM_TOTAL (W_BYTES + 2*SLOT_BYTES)   // 98816 -> 2 CTAs/SM
#define CHUNKS (SLOT_BYTES/16)         // 2064

typedef unsigned long long ull;

__device__ __forceinline__ void ffma2(ull &d, ull a, ull b) {
    asm("fma.rn.f32x2 %0, %1, %2, %0;" : "+l"(d) : "l"(a), "l"(b));
}
__device__ __forceinline__ float flo(ull v){ return __uint_as_float((unsigned)(v & 0xffffffffu)); }
__device__ __forceinline__ float fhi(ull v){ return __uint_as_float((unsigned)(v >> 32)); }

__device__ __forceinline__ void cp16(uint32_t sa, const void* g) {
    asm volatile("cp.async.cg.shared.global [%0], [%1], 16;" :: "r"(sa), "l"(g));
}
__device__ __forceinline__ void cp_commit() { asm volatile("cp.async.commit_group;"); }
__device__ __forceinline__ void cp_wait1()  { asm volatile("cp.async.wait_group 1;"); }

// stage s: unit iu = s/8, k-eighth q = s&7. Always commits (empty groups past
// the end keep wait_group(1) bookkeeping uniform). Address math amortized
// over 2064 cp.async chunks.
__device__ __forceinline__ void issue_stage(char* ring, const float* __restrict__ x,
                                            int s, int tid, int bx)
{
    if (s < NSTAGES) {
        const int u  = bx * UNITS_PER_BLOCK + (s >> 3);   // < 512
        const int q  = s & 7;
        const int bc = u >> 5;               // 32 units per bc
        const int U  = u & 31;
        const int f0 = 128 * U - 1;          // first staged frame (may be OOB)
        const float* xb = x + (size_t)bc * FRAMES * E_DIM + q * 64;
        char* slot = ring + (s & 1) * SLOT_BYTES;
        uint32_t sbase = (uint32_t)__cvta_generic_to_shared(slot);
#pragma unroll
        for (int i = 0; i < 9; i++) {
            int c = tid + i * NTH;
            if (i < 8 || c < CHUNKS) {
                int f = f0 + (c >> 4);       // 16 chunks of 16B per 256B row
                uint32_t sa = sbase + c * 16;
                if ((unsigned)f < FRAMES) {
                    cp16(sa, xb + (size_t)f * E_DIM + (c & 15) * 4);
                } else {
                    asm volatile("st.shared.v4.b32 [%0], {%1,%1,%1,%1};" :: "r"(sa), "r"(0));
                }
            }
        }
    }
    cp_commit();
}

__global__ __launch_bounds__(NTH, 2)
void decoder_fat2(const float* __restrict__ x,
                  const float* __restrict__ wt,
                  float* __restrict__ out)
{
    extern __shared__ __align__(16) char smem[];
    float* wsm = (float*)smem;
    char*  ring = smem + W_BYTES;

    const int tid = threadIdx.x;
    const int bx  = blockIdx.x;

    // stage weights (8 float4 per thread)
#pragma unroll
    for (int i = 0; i < (16 * E_DIM) / (4 * NTH); i++) {
        int idx = (i * NTH + tid) * 4;
        *(float4*)(wsm + idx) = *(const float4*)(wt + idx);
    }

    // prologue: prefetch stages 0,1
    issue_stage(ring, x, 0, tid, bx);
    issue_stage(ring, x, 1, tid, bx);

    const int lane = tid & 31;
    const int ks   = lane & 7;          // lane bits 0-2: k slice
    const int gl   = lane >> 3;         // lane bits 3-4: 2-pair group in warp
    const int gloc = (tid >> 5) * 4 + gl;    // group 0..31 within unit
    // thread tile: pairs 2*gloc, 2*gloc+1 ; ALL 16 weight rows

#pragma unroll 1
    for (int iu = 0; iu < UNITS_PER_BLOCK; iu++) {
        const int u  = bx * UNITS_PER_BLOCK + iu;
        const int bc = u >> 5;
        const int U  = u & 31;
        const int p0 = 64 * U + 2 * gloc;        // thread's first pair

        ull a0[8], a1[8], b0[8], b1[8];
#pragma unroll
        for (int j = 0; j < 8; j++) { a0[j]=0; a1[j]=0; b0[j]=0; b1[j]=0; }

#pragma unroll 1
        for (int q = 0; q < 8; q++) {
            const int s = 8 * iu + q;
            cp_wait1();
            __syncthreads();                     // stage s resident for all

            // rows 4*gloc..4*gloc+4 hold frames 2p0-1..2p0+3 (zeros OOB)
            const char* xg = ring + (s & 1) * SLOT_BYTES + (4 * gloc) * 256 + ks * 16;
            const float* wq = wsm + q * 64 + ks * 4;

#pragma unroll
            for (int i = 0; i < 2; i++) {
                const int xo = i * 128;          // 32 floats per granule
                ulonglong2 xm1 = *(const ulonglong2*)(xg +           xo);
                ulonglong2 x0  = *(const ulonglong2*)(xg + 1 * 256 + xo);
                ulonglong2 x1  = *(const ulonglong2*)(xg + 2 * 256 + xo);
                ulonglong2 x2  = *(const ulonglong2*)(xg + 3 * 256 + xo);
                ulonglong2 x3  = *(const ulonglong2*)(xg + 4 * 256 + xo);
#pragma unroll
                for (int j = 0; j < 8; j++) {
                    ulonglong2 wl = *(const ulonglong2*)(wq + j * E_DIM + i * 32);
                    ulonglong2 wh = *(const ulonglong2*)(wq + (j + 8) * E_DIM + i * 32);
                    ffma2(a0[j], x0.x,  wl.x);  ffma2(a0[j], x0.y,  wl.y);
                    ffma2(a0[j], xm1.x, wh.x);  ffma2(a0[j], xm1.y, wh.y);
                    ffma2(a1[j], x1.x,  wl.x);  ffma2(a1[j], x1.y,  wl.y);
                    ffma2(a1[j], x0.x,  wh.x);  ffma2(a1[j], x0.y,  wh.y);
                    ffma2(b0[j], x2.x,  wl.x);  ffma2(b0[j], x2.y,  wl.y);
                    ffma2(b0[j], x1.x,  wh.x);  ffma2(b0[j], x1.y,  wh.y);
                    ffma2(b1[j], x3.x,  wl.x);  ffma2(b1[j], x3.y,  wl.y);
                    ffma2(b1[j], x2.x,  wh.x);  ffma2(b1[j], x2.y,  wh.y);
                }
            }
            __syncthreads();                     // slot fully consumed
            issue_stage(ring, x, s + 2, tid, bx);   // refill (or empty commit)
        }

        // epilogue: packed horizontal add, reduce over the 8 ks lanes
        float sv[32];
#pragma unroll
        for (int j = 0; j < 8; j++) {
            sv[j]      = flo(a0[j]) + fhi(a0[j]);
            sv[8 + j]  = flo(a1[j]) + fhi(a1[j]);
            sv[16 + j] = flo(b0[j]) + fhi(b0[j]);
            sv[24 + j] = flo(b1[j]) + fhi(b1[j]);
        }
#pragma unroll
        for (int m = 1; m <= 4; m <<= 1)
#pragma unroll
            for (int j = 0; j < 32; j++)
                sv[j] += __shfl_xor_sync(0xffffffffu, sv[j], m);

        if (ks == 0 && p0 < PAIRS) {
            float* o = out + (size_t)bc * OUT_T + (size_t)p0 * 16;  // 32 floats
#pragma unroll
            for (int qq = 0; qq < 8; qq++)
                *(float4*)(o + 4 * qq) =
                    make_float4(sv[4*qq], sv[4*qq+1], sv[4*qq+2], sv[4*qq+3]);
        }
    }
}

extern "C" void kernel_launch(void* const* d_in, const int* in_sizes, int n_in,
                              void* d_out, int out_size)
{
    const float *x, *wt;
    if (in_sizes[0] > in_sizes[1]) { x = (const float*)d_in[0]; wt = (const float*)d_in[1]; }
    else                           { x = (const float*)d_in[1]; wt = (const float*)d_in[0]; }

    cudaFuncSetAttribute(decoder_fat2,
                         cudaFuncAttributeMaxDynamicSharedMemorySize, SMEM_TOTAL);

    decoder_fat2<<<GRID, NTH, SMEM_TOTAL>>>(x, wt, (float*)d_out);
}